// round 6
// baseline (speedup 1.0000x reference)
#include <cuda_runtime.h>

#define EMB   768
#define HEADS 8
#define HDIM  96
#define BATCH 4
#define SEQ   2048
#define ROWS  (BATCH*SEQ)      /* 8192 */
#define QKV_N (3*EMB)          /* 2304 */
#define INV_SCALE 0.10206207261596577f   /* 1/sqrt(96) */

typedef unsigned long long ull;

// ---------------- scratch (static device globals: allocation-free) ----------
__device__ float g_q[BATCH*HEADS*SEQ*HDIM];
__device__ float g_k[BATCH*HEADS*SEQ*HDIM];
__device__ float g_v[BATCH*HEADS*SEQ*HDIM];
__device__ float g_attn[ROWS*EMB];

// ---------------- f32x2 helpers (Blackwell packed fp32, PTX-only) -----------
__device__ __forceinline__ ull pack2(float lo, float hi){
    ull r; asm("mov.b64 %0, {%1, %2};" : "=l"(r) : "f"(lo), "f"(hi)); return r;
}
__device__ __forceinline__ void unpack2(ull v, float& lo, float& hi){
    asm("mov.b64 {%0, %1}, %2;" : "=f"(lo), "=f"(hi) : "l"(v));
}
__device__ __forceinline__ ull fma2(ull a, ull b, ull c){
    ull d; asm("fma.rn.f32x2 %0, %1, %2, %3;" : "=l"(d) : "l"(a), "l"(b), "l"(c)); return d;
}
__device__ __forceinline__ ull mul2(ull a, ull b){
    ull d; asm("mul.rn.f32x2 %0, %1, %2;" : "=l"(d) : "l"(a), "l"(b)); return d;
}

// ============================================================================
// SGEMM: C[M x NC] = A[M x 768] * B[768 x NC] + bias
//   MODE 0: A = x, result scattered into g_q/g_k/g_v per qkv column decode
//   MODE 1: A = g_attn, result written densely to C (= d_out)
// Tile 64x64xBK16, 256 threads (16x16), 4x4 micro-tile via f32x2 pairs.
// ============================================================================
template<int NC, int MODE>
__global__ void __launch_bounds__(256) sgemm_kernel(const float* __restrict__ A,
                                                    const float* __restrict__ B,
                                                    const float* __restrict__ bias,
                                                    float* __restrict__ C)
{
    __shared__ float As[16*64];   // k-major: As[k][m]
    __shared__ float Bs[16*64];   // k-major: Bs[k][n]

    const int tx = threadIdx.x, ty = threadIdx.y;
    const int tid = ty*16 + tx;
    const int bx = blockIdx.x, by = blockIdx.y;

    const float* Asrc = (MODE == 0) ? A : (const float*)g_attn;

    const int arow = tid >> 2;          // 0..63
    const int ac4  = (tid & 3) << 2;    // 0,4,8,12
    const int brow = tid >> 4;          // 0..15
    const int bc4  = (tid & 15) << 2;   // 0..60

    const float* Ap = Asrc + (size_t)(by*64 + arow)*EMB + ac4;
    const float* Bp = B + (size_t)brow*NC + bx*64 + bc4;

    ull acc[4][2];
    #pragma unroll
    for (int i = 0; i < 4; ++i){ acc[i][0] = 0ull; acc[i][1] = 0ull; }

    float4 av = *(const float4*)Ap;
    float4 bv = *(const float4*)Bp;

    for (int kt = 0; kt < EMB/16; ++kt){
        // stage current tile
        As[(ac4+0)*64 + arow] = av.x;
        As[(ac4+1)*64 + arow] = av.y;
        As[(ac4+2)*64 + arow] = av.z;
        As[(ac4+3)*64 + arow] = av.w;
        *(float4*)&Bs[brow*64 + bc4] = bv;
        __syncthreads();

        // prefetch next tile (hide global latency under FMA work)
        if (kt + 1 < EMB/16){
            av = *(const float4*)(Ap + (kt+1)*16);
            bv = *(const float4*)(Bp + (size_t)(kt+1)*16*NC);
        }

        #pragma unroll
        for (int k = 0; k < 16; ++k){
            float4 a = *(float4*)&As[k*64 + 4*ty];   // 4 rows  (broadcast)
            float4 b = *(float4*)&Bs[k*64 + 4*tx];   // 4 cols  (coalesced)
            ull b0 = pack2(b.x, b.y);
            ull b1 = pack2(b.z, b.w);
            float aa[4] = {a.x, a.y, a.z, a.w};
            #pragma unroll
            for (int i = 0; i < 4; ++i){
                ull ad = pack2(aa[i], aa[i]);
                acc[i][0] = fma2(ad, b0, acc[i][0]);
                acc[i][1] = fma2(ad, b1, acc[i][1]);
            }
        }
        __syncthreads();
    }

    // ----- epilogue -----
    #pragma unroll
    for (int i = 0; i < 4; ++i){
        const int m = by*64 + 4*ty + i;
        #pragma unroll
        for (int j2 = 0; j2 < 2; ++j2){
            float lo, hi; unpack2(acc[i][j2], lo, hi);
            const int c0 = bx*64 + 4*tx + 2*j2;
            const float v0 = lo + bias[c0];
            const float v1 = hi + bias[c0+1];
            if (MODE == 1){
                C[(size_t)m*NC + c0]     = v0;
                C[(size_t)m*NC + c0 + 1] = v1;
            } else {
                const int b = m >> 11;        // /2048
                const int n = m & 2047;
                #pragma unroll
                for (int e = 0; e < 2; ++e){
                    const int c = c0 + e;
                    const float val = e ? v1 : v0;
                    // qkv reshape (B,N,H,D,3): c = h*288 + d*3 + which
                    const int which = c % 3;
                    const int t     = c / 3;
                    const int d     = t % HDIM;
                    const int h     = t / HDIM;
                    float* dst = (which == 0) ? g_q : (which == 1) ? g_k : g_v;
                    dst[((size_t)(b*HEADS + h)*SEQ + n)*HDIM + d] = val;
                }
            }
        }
    }
}

// ============================================================================
// Flash attention (fp32, online softmax). One block = (bh, 64-query tile).
// Q/K k-major in SMEM (stride 68), V row-major, P staged row-major.
// S micro-tile 4x4 (f32x2 over key cols); PV pairs adjacent d columns so V
// loads are conflict-free LDS.64. softmax(S) applied, 1/sqrt(D) AFTER.
// ============================================================================
__global__ void __launch_bounds__(256, 2) flash_kernel()
{
    extern __shared__ float smf[];
    float* Qs = smf;                 // 96*68
    float* Ks = Qs + 96*68;          // 96*68
    float* Vs = Ks + 96*68;          // 64*96
    float* Ps = Vs + 64*96;          // 64*64

    const int tx = threadIdx.x, ty = threadIdx.y;
    const int tid = ty*16 + tx;
    const int n0 = blockIdx.x * 64;
    const int bh = blockIdx.y;

    const float* Qg = g_q + (size_t)bh*SEQ*HDIM;
    const float* Kg = g_k + (size_t)bh*SEQ*HDIM;
    const float* Vg = g_v + (size_t)bh*SEQ*HDIM;

    // load Q tile (64x96) transposed to k-major
    #pragma unroll
    for (int it = 0; it < 6; ++it){
        int idx4 = tid + it*256;          // 0..1535
        int r  = idx4 / 24;
        int d4 = (idx4 % 24) * 4;
        float4 v = *(const float4*)&Qg[(size_t)(n0 + r)*HDIM + d4];
        Qs[(d4+0)*68 + r] = v.x;
        Qs[(d4+1)*68 + r] = v.y;
        Qs[(d4+2)*68 + r] = v.z;
        Qs[(d4+3)*68 + r] = v.w;
    }

    ull o2[4][3];
    float m[4], l[4];
    #pragma unroll
    for (int i = 0; i < 4; ++i){
        m[i] = -1e30f; l[i] = 0.f;
        o2[i][0] = 0ull; o2[i][1] = 0ull; o2[i][2] = 0ull;
    }

    for (int t = 0; t < SEQ/64; ++t){
        __syncthreads();   // previous PV done (also orders initial Qs stores)

        const int kn0 = t*64;
        #pragma unroll
        for (int it = 0; it < 6; ++it){
            int idx4 = tid + it*256;
            int r  = idx4 / 24;
            int d4 = (idx4 % 24) * 4;
            float4 kv = *(const float4*)&Kg[(size_t)(kn0 + r)*HDIM + d4];
            Ks[(d4+0)*68 + r] = kv.x;
            Ks[(d4+1)*68 + r] = kv.y;
            Ks[(d4+2)*68 + r] = kv.z;
            Ks[(d4+3)*68 + r] = kv.w;
            *(float4*)&Vs[r*HDIM + d4] = *(const float4*)&Vg[(size_t)(kn0 + r)*HDIM + d4];
        }
        __syncthreads();

        // ---- S = Q * K^T (64x64 tile), 4x4 per thread ----
        ull s2[4][2];
        #pragma unroll
        for (int i = 0; i < 4; ++i){ s2[i][0] = 0ull; s2[i][1] = 0ull; }

        #pragma unroll 6
        for (int k = 0; k < HDIM; ++k){
            float4 q  = *(float4*)&Qs[k*68 + 4*ty];
            float4 kk = *(float4*)&Ks[k*68 + 4*tx];
            ull b0 = pack2(kk.x, kk.y);
            ull b1 = pack2(kk.z, kk.w);
            float qa[4] = {q.x, q.y, q.z, q.w};
            #pragma unroll
            for (int i = 0; i < 4; ++i){
                ull qd = pack2(qa[i], qa[i]);
                s2[i][0] = fma2(qd, b0, s2[i][0]);
                s2[i][1] = fma2(qd, b1, s2[i][1]);
            }
        }

        // ---- online softmax (row groups owned by half-warp, width-16 shfl) ----
        #pragma unroll
        for (int i = 0; i < 4; ++i){
            float s0, s1, s2v, s3;
            unpack2(s2[i][0], s0, s1);
            unpack2(s2[i][1], s2v, s3);
            float tm = fmaxf(fmaxf(s0, s1), fmaxf(s2v, s3));
            #pragma unroll
            for (int off = 8; off > 0; off >>= 1)
                tm = fmaxf(tm, __shfl_xor_sync(0xffffffffu, tm, off, 16));
            const float mnew  = fmaxf(m[i], tm);
            const float alpha = __expf(m[i] - mnew);
            const float p0 = __expf(s0  - mnew);
            const float p1 = __expf(s1  - mnew);
            const float p2 = __expf(s2v - mnew);
            const float p3 = __expf(s3  - mnew);
            float rs = (p0 + p1) + (p2 + p3);
            #pragma unroll
            for (int off = 8; off > 0; off >>= 1)
                rs += __shfl_xor_sync(0xffffffffu, rs, off, 16);
            l[i] = l[i]*alpha + rs;
            m[i] = mnew;
            const ull a2 = pack2(alpha, alpha);
            o2[i][0] = mul2(a2, o2[i][0]);
            o2[i][1] = mul2(a2, o2[i][1]);
            o2[i][2] = mul2(a2, o2[i][2]);
            *(float4*)&Ps[(4*ty + i)*64 + 4*tx] = make_float4(p0, p1, p2, p3);
        }
        __syncthreads();

        // ---- O += P * V ; thread owns rows 4ty..+3, d in {2tx,2tx+1}+32*j2 ----
        #pragma unroll 2
        for (int kk0 = 0; kk0 < 64; kk0 += 4){
            float4 pr[4];
            #pragma unroll
            for (int i = 0; i < 4; ++i)
                pr[i] = *(float4*)&Ps[(4*ty + i)*64 + kk0];
            #pragma unroll
            for (int u = 0; u < 4; ++u){
                const int kk = kk0 + u;
                ull v0 = *(const ull*)&Vs[kk*HDIM + 2*tx];
                ull v1 = *(const ull*)&Vs[kk*HDIM + 2*tx + 32];
                ull v2 = *(const ull*)&Vs[kk*HDIM + 2*tx + 64];
                #pragma unroll
                for (int i = 0; i < 4; ++i){
                    const float pv = ((const float*)&pr[i])[u];
                    const ull pd = pack2(pv, pv);
                    o2[i][0] = fma2(pd, v0, o2[i][0]);
                    o2[i][1] = fma2(pd, v1, o2[i][1]);
                    o2[i][2] = fma2(pd, v2, o2[i][2]);
                }
            }
        }
    }

    // ---- normalize, apply post-softmax inv_scale, write b n (h d) layout ----
    const int b = bh / HEADS, h = bh % HEADS;
    #pragma unroll
    for (int i = 0; i < 4; ++i){
        const float sc = INV_SCALE / l[i];
        float* dst = g_attn + (size_t)(b*SEQ + n0 + 4*ty + i)*EMB + h*HDIM;
        #pragma unroll
        for (int j2 = 0; j2 < 3; ++j2){
            float lo, hi; unpack2(o2[i][j2], lo, hi);
            dst[2*tx + 32*j2 + 0] = lo * sc;
            dst[2*tx + 32*j2 + 1] = hi * sc;
        }
    }
}

// ============================================================================
extern "C" void kernel_launch(void* const* d_in, const int* in_sizes, int n_in,
                              void* d_out, int out_size)
{
    const float* x      = (const float*)d_in[0];
    const float* w_qkv  = (const float*)d_in[1];
    const float* b_qkv  = (const float*)d_in[2];
    const float* w_proj = (const float*)d_in[3];
    const float* b_proj = (const float*)d_in[4];
    float* out = (float*)d_out;

    const int smem = (96*68 + 96*68 + 64*96 + 64*64) * (int)sizeof(float); // 93184
    cudaFuncSetAttribute(flash_kernel, cudaFuncAttributeMaxDynamicSharedMemorySize, smem);

    dim3 blk(16, 16);
    // 1) QKV GEMM + bias + scatter to [b,h,n,d]
    sgemm_kernel<QKV_N, 0><<<dim3(QKV_N/64, ROWS/64), blk>>>(x, w_qkv, b_qkv, nullptr);
    // 2) flash attention per (b*h, 64-query tile); qt fastest -> L2 K/V reuse
    flash_kernel<<<dim3(SEQ/64, BATCH*HEADS), blk, smem>>>();
    // 3) output projection + bias
    sgemm_kernel<EMB, 1><<<dim3(EMB/64, ROWS/64), blk>>>(nullptr, w_proj, b_proj, out);
}

// round 7
// speedup vs baseline: 1.3051x; 1.3051x over previous
#include <cuda_runtime.h>

#define EMB   768
#define HEADS 8
#define HDIM  96
#define BATCH 4
#define SEQ   2048
#define ROWS  (BATCH*SEQ)      /* 8192 */
#define QKV_N (3*EMB)          /* 2304 */
#define INV_SCALE 0.10206207261596577f   /* 1/sqrt(96) */

typedef unsigned long long ull;

// ---------------- scratch (static device globals: allocation-free) ----------
// q, k stored d-major [bh][d][n] so flash staging is conflict-free direct copy.
__device__ float g_q[BATCH*HEADS*HDIM*SEQ];
__device__ float g_k[BATCH*HEADS*HDIM*SEQ];
// v stays n-major [bh][n][d] (PV consumes V rows along d).
__device__ float g_v[BATCH*HEADS*SEQ*HDIM];
__device__ float g_attn[ROWS*EMB];

// ---------------- f32x2 helpers (Blackwell packed fp32, PTX-only) -----------
__device__ __forceinline__ ull pack2(float lo, float hi){
    ull r; asm("mov.b64 %0, {%1, %2};" : "=l"(r) : "f"(lo), "f"(hi)); return r;
}
__device__ __forceinline__ void unpack2(ull v, float& lo, float& hi){
    asm("mov.b64 {%0, %1}, %2;" : "=f"(lo), "=f"(hi) : "l"(v));
}
__device__ __forceinline__ ull fma2(ull a, ull b, ull c){
    ull d; asm("fma.rn.f32x2 %0, %1, %2, %3;" : "=l"(d) : "l"(a), "l"(b), "l"(c)); return d;
}
__device__ __forceinline__ ull mul2(ull a, ull b){
    ull d; asm("mul.rn.f32x2 %0, %1, %2;" : "=l"(d) : "l"(a), "l"(b)); return d;
}

// ============================================================================
// SGEMM: C[M x NC] = A[M x 768] * B[768 x NC] + bias
//   MODE 0: A = x, scatter into g_q/g_k (d-major) and g_v (n-major)
//   MODE 1: A = g_attn, dense write to C (= d_out)
// Tile 128x128x16, 256 threads, 8x8 micro-tile via f32x2 pairs.
// Per k per warp: 4 LDS.128 (16 wf) : 32 FFMA2 (64 issue) -> L1 == FMA balanced.
// ============================================================================
template<int NC, int MODE>
__global__ void __launch_bounds__(256) sgemm_kernel(const float* __restrict__ A,
                                                    const float* __restrict__ B,
                                                    const float* __restrict__ bias,
                                                    float* __restrict__ C)
{
    __shared__ __align__(16) float As[16*132];   // k-major: As[k][m], pad 132
    __shared__ __align__(16) float Bs[16*128];   // k-major: Bs[k][n]

    const int tx = threadIdx.x, ty = threadIdx.y;
    const int tid = ty*16 + tx;
    const int bx = blockIdx.x, by = blockIdx.y;

    const float* Asrc = (MODE == 0) ? A : (const float*)g_attn;

    // staging assignment
    const int am = tid >> 2;            // 0..63 (rows am and am+64)
    const int ak = (tid & 3) << 2;      // 0,4,8,12
    const int bk = tid >> 5;            // 0..7  (k rows bk and bk+8)
    const int bn = (tid & 31) << 2;     // 0..124

    const float* Ap = Asrc + (size_t)(by*128 + am)*EMB + ak;
    const float* Bp = B + (size_t)bk*NC + bx*128 + bn;

    ull acc[8][4];
    #pragma unroll
    for (int i = 0; i < 8; ++i)
        #pragma unroll
        for (int j = 0; j < 4; ++j) acc[i][j] = 0ull;

    float4 a0 = *(const float4*)Ap;
    float4 a1 = *(const float4*)(Ap + 64*EMB);
    float4 b0 = *(const float4*)Bp;
    float4 b1 = *(const float4*)(Bp + 8*NC);

    for (int kt = 0; kt < EMB/16; ++kt){
        // stage current tile
        As[(ak+0)*132 + am] = a0.x;  As[(ak+1)*132 + am] = a0.y;
        As[(ak+2)*132 + am] = a0.z;  As[(ak+3)*132 + am] = a0.w;
        As[(ak+0)*132 + am + 64] = a1.x;  As[(ak+1)*132 + am + 64] = a1.y;
        As[(ak+2)*132 + am + 64] = a1.z;  As[(ak+3)*132 + am + 64] = a1.w;
        *(float4*)&Bs[bk*128 + bn]     = b0;
        *(float4*)&Bs[(bk+8)*128 + bn] = b1;
        __syncthreads();

        // prefetch next tile
        if (kt + 1 < EMB/16){
            a0 = *(const float4*)(Ap + (kt+1)*16);
            a1 = *(const float4*)(Ap + 64*EMB + (kt+1)*16);
            b0 = *(const float4*)(Bp + (size_t)((kt+1)*16)*NC);
            b1 = *(const float4*)(Bp + (size_t)((kt+1)*16 + 8)*NC);
        }

        #pragma unroll
        for (int k = 0; k < 16; ++k){
            float4 xa = *(float4*)&As[k*132 + 4*ty];
            float4 xb = *(float4*)&As[k*132 + 64 + 4*ty];
            ulonglong2 ya = *(const ulonglong2*)&Bs[k*128 + 4*tx];
            ulonglong2 yb = *(const ulonglong2*)&Bs[k*128 + 64 + 4*tx];
            float av8[8] = {xa.x, xa.y, xa.z, xa.w, xb.x, xb.y, xb.z, xb.w};
            #pragma unroll
            for (int i = 0; i < 8; ++i){
                ull ad = pack2(av8[i], av8[i]);
                acc[i][0] = fma2(ad, ya.x, acc[i][0]);
                acc[i][1] = fma2(ad, ya.y, acc[i][1]);
                acc[i][2] = fma2(ad, yb.x, acc[i][2]);
                acc[i][3] = fma2(ad, yb.y, acc[i][3]);
            }
        }
        __syncthreads();
    }

    // ----- epilogue -----
    #pragma unroll
    for (int i = 0; i < 8; ++i){
        const int m = by*128 + ((i < 4) ? (4*ty + i) : (64 + 4*ty + i - 4));
        #pragma unroll
        for (int j = 0; j < 4; ++j){
            float lo, hi; unpack2(acc[i][j], lo, hi);
            const int c0 = bx*128 + ((j < 2) ? 4*tx : (64 + 4*tx)) + 2*(j & 1);
            const float v0 = lo + bias[c0];
            const float v1 = hi + bias[c0+1];
            if (MODE == 1){
                C[(size_t)m*NC + c0]     = v0;
                C[(size_t)m*NC + c0 + 1] = v1;
            } else {
                const int b = m >> 11;       // /2048
                const int n = m & 2047;
                #pragma unroll
                for (int e = 0; e < 2; ++e){
                    const int c = c0 + e;
                    const float val = e ? v1 : v0;
                    // qkv reshape (B,N,H,D,3): c = h*288 + d*3 + which
                    const int which = c % 3;
                    const int t     = c / 3;
                    const int d     = t % HDIM;
                    const int h     = t / HDIM;
                    const int bh    = b*HEADS + h;
                    if (which == 2)
                        g_v[((size_t)bh*SEQ + n)*HDIM + d] = val;          // [bh][n][d]
                    else {
                        float* dst = (which == 0) ? g_q : g_k;
                        dst[((size_t)bh*HDIM + d)*SEQ + n] = val;          // [bh][d][n]
                    }
                }
            }
        }
    }
}

// ============================================================================
// Flash attention, fp32 online softmax. One block = (bh, 128-query tile).
// 128x128 S tile, 8x8 micro; PV: 8 rows x 6 d-cols (3 ull). 208KB smem,
// 1 block/SM (8 warps). Q/K staged d-major (no transpose, no pad).
// softmax(S) applied, 1/sqrt(D) AFTER (faithful to reference).
// ============================================================================
__global__ void __launch_bounds__(256, 1) flash_kernel()
{
    extern __shared__ __align__(16) float smf[];
    float* Qs = smf;                 // [96][128]  k-major
    float* Ks = Qs + 96*128;         // [96][128]  k-major
    float* Vs = Ks + 96*128;         // [128][96]  n-major
    float* Ps = Vs + 128*96;         // [128][128] row-major

    const int tx = threadIdx.x, ty = threadIdx.y;
    const int tid = ty*16 + tx;
    const int n0 = blockIdx.x * 128;
    const int bh = blockIdx.y;

    const float* Qg = g_q + (size_t)bh*HDIM*SEQ;
    const float* Kg = g_k + (size_t)bh*HDIM*SEQ;
    const float* Vg = g_v + (size_t)bh*SEQ*HDIM;

    int row8[8];
    #pragma unroll
    for (int i = 0; i < 8; ++i) row8[i] = (i < 4) ? (4*ty + i) : (64 + 4*ty + i - 4);

    // load Q tile [96][128] — direct copy, conflict-free
    #pragma unroll
    for (int it = 0; it < 12; ++it){
        int f  = tid + it*256;         // 0..3071
        int d  = f >> 5;
        int n4 = (f & 31) << 2;
        *(float4*)&Qs[d*128 + n4] = *(const float4*)&Qg[(size_t)d*SEQ + n0 + n4];
    }

    ull o2[8][3];
    float mx[8], l[8];
    #pragma unroll
    for (int i = 0; i < 8; ++i){
        mx[i] = -1e30f; l[i] = 0.f;
        o2[i][0] = 0ull; o2[i][1] = 0ull; o2[i][2] = 0ull;
    }

    #pragma unroll 1
    for (int t = 0; t < SEQ/128; ++t){
        __syncthreads();   // prev iter done reading Ks/Vs/Ps (+ initial Qs order)

        const int kn0 = t*128;
        #pragma unroll
        for (int it = 0; it < 12; ++it){
            int f  = tid + it*256;
            int d  = f >> 5;
            int n4 = (f & 31) << 2;
            *(float4*)&Ks[d*128 + n4] = *(const float4*)&Kg[(size_t)d*SEQ + kn0 + n4];
            int r  = f / 24;
            int d4 = (f % 24) << 2;
            *(float4*)&Vs[r*HDIM + d4] = *(const float4*)&Vg[(size_t)(kn0 + r)*HDIM + d4];
        }
        __syncthreads();

        // ---- S = Q * K^T (128x128 tile), 8x8 per thread ----
        ull s2[8][4];
        #pragma unroll
        for (int i = 0; i < 8; ++i)
            #pragma unroll
            for (int j = 0; j < 4; ++j) s2[i][j] = 0ull;

        #pragma unroll 4
        for (int k = 0; k < HDIM; ++k){
            float4 qa = *(float4*)&Qs[k*128 + 4*ty];
            float4 qb = *(float4*)&Qs[k*128 + 64 + 4*ty];
            ulonglong2 ka = *(const ulonglong2*)&Ks[k*128 + 4*tx];
            ulonglong2 kb = *(const ulonglong2*)&Ks[k*128 + 64 + 4*tx];
            float qv[8] = {qa.x, qa.y, qa.z, qa.w, qb.x, qb.y, qb.z, qb.w};
            #pragma unroll
            for (int i = 0; i < 8; ++i){
                ull qd = pack2(qv[i], qv[i]);
                s2[i][0] = fma2(qd, ka.x, s2[i][0]);
                s2[i][1] = fma2(qd, ka.y, s2[i][1]);
                s2[i][2] = fma2(qd, kb.x, s2[i][2]);
                s2[i][3] = fma2(qd, kb.y, s2[i][3]);
            }
        }

        // ---- online softmax (rows owned by 16-lane group, width-16 shfl) ----
        #pragma unroll
        for (int i = 0; i < 8; ++i){
            float s[8];
            unpack2(s2[i][0], s[0], s[1]);
            unpack2(s2[i][1], s[2], s[3]);
            unpack2(s2[i][2], s[4], s[5]);
            unpack2(s2[i][3], s[6], s[7]);
            float tm = fmaxf(fmaxf(fmaxf(s[0], s[1]), fmaxf(s[2], s[3])),
                             fmaxf(fmaxf(s[4], s[5]), fmaxf(s[6], s[7])));
            #pragma unroll
            for (int off = 8; off > 0; off >>= 1)
                tm = fmaxf(tm, __shfl_xor_sync(0xffffffffu, tm, off, 16));
            const float mnew  = fmaxf(mx[i], tm);
            const float alpha = __expf(mx[i] - mnew);
            float p[8], rs = 0.f;
            #pragma unroll
            for (int u = 0; u < 8; ++u){ p[u] = __expf(s[u] - mnew); rs += p[u]; }
            #pragma unroll
            for (int off = 8; off > 0; off >>= 1)
                rs += __shfl_xor_sync(0xffffffffu, rs, off, 16);
            l[i] = l[i]*alpha + rs;
            mx[i] = mnew;
            const ull a2 = pack2(alpha, alpha);
            o2[i][0] = mul2(a2, o2[i][0]);
            o2[i][1] = mul2(a2, o2[i][1]);
            o2[i][2] = mul2(a2, o2[i][2]);
            *(float4*)&Ps[row8[i]*128 + 4*tx]      = make_float4(p[0], p[1], p[2], p[3]);
            *(float4*)&Ps[row8[i]*128 + 64 + 4*tx] = make_float4(p[4], p[5], p[6], p[7]);
        }
        __syncthreads();

        // ---- O += P * V ; rows row8[i], d in {2tx, 2tx+32, 2tx+64} ----
        #pragma unroll 1
        for (int kk0 = 0; kk0 < 128; kk0 += 4){
            float4 pr[8];
            #pragma unroll
            for (int i = 0; i < 8; ++i)
                pr[i] = *(float4*)&Ps[row8[i]*128 + kk0];
            #pragma unroll
            for (int u = 0; u < 4; ++u){
                const int kk = kk0 + u;
                ull v0 = *(const ull*)&Vs[kk*HDIM + 2*tx];
                ull v1 = *(const ull*)&Vs[kk*HDIM + 2*tx + 32];
                ull v2 = *(const ull*)&Vs[kk*HDIM + 2*tx + 64];
                #pragma unroll
                for (int i = 0; i < 8; ++i){
                    const float pv = ((const float*)&pr[i])[u];
                    const ull pd = pack2(pv, pv);
                    o2[i][0] = fma2(pd, v0, o2[i][0]);
                    o2[i][1] = fma2(pd, v1, o2[i][1]);
                    o2[i][2] = fma2(pd, v2, o2[i][2]);
                }
            }
        }
    }

    // ---- normalize, apply post-softmax inv_scale, write b n (h d) layout ----
    const int b = bh / HEADS, h = bh % HEADS;
    #pragma unroll
    for (int i = 0; i < 8; ++i){
        const float sc = INV_SCALE / l[i];
        float* dst = g_attn + (size_t)(b*SEQ + n0 + row8[i])*EMB + h*HDIM;
        #pragma unroll
        for (int j = 0; j < 3; ++j){
            float lo, hi; unpack2(o2[i][j], lo, hi);
            dst[2*tx + 32*j + 0] = lo * sc;
            dst[2*tx + 32*j + 1] = hi * sc;
        }
    }
}

// ============================================================================
extern "C" void kernel_launch(void* const* d_in, const int* in_sizes, int n_in,
                              void* d_out, int out_size)
{
    const float* x      = (const float*)d_in[0];
    const float* w_qkv  = (const float*)d_in[1];
    const float* b_qkv  = (const float*)d_in[2];
    const float* w_proj = (const float*)d_in[3];
    const float* b_proj = (const float*)d_in[4];
    float* out = (float*)d_out;

    const int smem = (96*128 + 96*128 + 128*96 + 128*128) * (int)sizeof(float); // 212992
    cudaFuncSetAttribute(flash_kernel, cudaFuncAttributeMaxDynamicSharedMemorySize, smem);

    dim3 blk(16, 16);
    // 1) QKV GEMM + bias + scatter (q,k d-major; v n-major)
    sgemm_kernel<QKV_N, 0><<<dim3(QKV_N/128, ROWS/128), blk>>>(x, w_qkv, b_qkv, nullptr);
    // 2) flash attention: (128-query tile, b*h)
    flash_kernel<<<dim3(SEQ/128, BATCH*HEADS), blk, smem>>>();
    // 3) output projection + bias
    sgemm_kernel<EMB, 1><<<dim3(EMB/128, ROWS/128), blk>>>(nullptr, w_proj, b_proj, out);
}